// round 1
// baseline (speedup 1.0000x reference)
#include <cuda_runtime.h>
#include <cuda_bf16.h>
#include <cstdint>

#define N_PROJ 400000
#define N_SP   40000
#define D_     256
#define H_     8

// -------- scratch (device globals; no runtime allocation allowed) --------
__device__ float g_xl[(size_t)N_PROJ * D_];    // proj @ Wl + bl
__device__ float g_xagg[(size_t)N_SP * D_];    // relu(LN1(prev))
__device__ float g_xr[(size_t)N_SP * D_];      // xagg @ Wr + br
__device__ float g_out[(size_t)N_SP * D_];     // sum_e ex * xl
__device__ float g_den[(size_t)N_SP * H_];     // sum_e ex
__device__ float g_xskip[(size_t)N_SP * D_];
__device__ float g_hbuf[(size_t)N_SP * D_];

// -------- zero the accumulators --------
__global__ void zero_kernel(float* out_acc, float* den_acc) {
    int i = blockIdx.x * blockDim.x + threadIdx.x;
    if (i < N_SP * D_) out_acc[i] = 0.f;
    if (i < N_SP * H_) den_acc[i] = 0.f;
}

// -------- LayerNorm + ReLU (one row per 256-thread block) --------
__global__ void ln_relu_kernel(const float* __restrict__ x,
                               const float* __restrict__ g,
                               const float* __restrict__ b,
                               float* __restrict__ out) {
    int row = blockIdx.x, t = threadIdx.x;
    size_t idx = (size_t)row * D_ + t;
    float v = x[idx];
    float s = v, q = v * v;
    #pragma unroll
    for (int o = 16; o; o >>= 1) {
        s += __shfl_xor_sync(0xffffffffu, s, o);
        q += __shfl_xor_sync(0xffffffffu, q, o);
    }
    __shared__ float ss[8], qq[8];
    if ((t & 31) == 0) { ss[t >> 5] = s; qq[t >> 5] = q; }
    __syncthreads();
    float tot = 0.f, totq = 0.f;
    #pragma unroll
    for (int w = 0; w < 8; w++) { tot += ss[w]; totq += qq[w]; }
    float mean = tot * (1.f / 256.f);
    float var  = totq * (1.f / 256.f) - mean * mean;
    float rstd = rsqrtf(var + 1e-5f);
    float y = (v - mean) * rstd * g[t] + b[t];
    out[idx] = fmaxf(y, 0.f);
}

// -------- SGEMM: C[M,256] = A[M,256] @ W[256,256] + bias (+skip) --------
// 64x64 block tile, BK=16, 256 threads, 4x4 register tile per thread.
__global__ void __launch_bounds__(256)
gemm256_kernel(const float* __restrict__ A, const float* __restrict__ W,
               const float* __restrict__ bias, const float* __restrict__ skip,
               float* __restrict__ C) {
    __shared__ float As[16][64];
    __shared__ float Bs[16][64];
    int tid  = threadIdx.x;
    int row0 = blockIdx.y * 64;
    int col0 = blockIdx.x * 64;
    int tx = tid & 15, ty = tid >> 4;

    int aRow = tid >> 2;            // 0..63
    int aCol = (tid & 3) << 2;      // 0,4,8,12
    int bRow = tid >> 4;            // 0..15
    int bCol = (tid & 15) << 2;     // 0..60

    const float* Aptr = A + (size_t)(row0 + aRow) * 256 + aCol;
    const float* Wptr = W + (size_t)bRow * 256 + col0 + bCol;

    float acc[4][4] = {};

    for (int k0 = 0; k0 < 256; k0 += 16) {
        float4 av = *(const float4*)(Aptr + k0);
        float4 bv = *(const float4*)(Wptr + (size_t)k0 * 256);
        As[aCol + 0][aRow] = av.x;
        As[aCol + 1][aRow] = av.y;
        As[aCol + 2][aRow] = av.z;
        As[aCol + 3][aRow] = av.w;
        *(float4*)&Bs[bRow][bCol] = bv;
        __syncthreads();
        #pragma unroll
        for (int k = 0; k < 16; k++) {
            float4 a = *(const float4*)&As[k][ty << 2];
            float4 b = *(const float4*)&Bs[k][tx << 2];
            acc[0][0] += a.x * b.x; acc[0][1] += a.x * b.y; acc[0][2] += a.x * b.z; acc[0][3] += a.x * b.w;
            acc[1][0] += a.y * b.x; acc[1][1] += a.y * b.y; acc[1][2] += a.y * b.z; acc[1][3] += a.y * b.w;
            acc[2][0] += a.z * b.x; acc[2][1] += a.z * b.y; acc[2][2] += a.z * b.z; acc[2][3] += a.z * b.w;
            acc[3][0] += a.w * b.x; acc[3][1] += a.w * b.y; acc[3][2] += a.w * b.z; acc[3][3] += a.w * b.w;
        }
        __syncthreads();
    }

    #pragma unroll
    for (int i = 0; i < 4; i++) {
        int r = row0 + (ty << 2) + i;
        #pragma unroll
        for (int j = 0; j < 4; j++) {
            int c = col0 + (tx << 2) + j;
            float v = acc[i][j] + bias[c];
            if (skip) v += skip[(size_t)r * 256 + c];
            C[(size_t)r * 256 + c] = v;
        }
    }
}

// -------- edge pass: one warp per edge --------
// score e[h] = sum_d leaky_relu(xl[src,h,d] + xr[tgt,h,d]) * att[h,d]
// ex = exp(e);  den[tgt,h] += ex;  out[tgt,h,d] += ex * xl[src,h,d]
__global__ void edge_kernel(const int* __restrict__ esrc,
                            const int* __restrict__ etgt,
                            const float* __restrict__ att,
                            const float* __restrict__ xl,
                            const float* __restrict__ xr,
                            float* __restrict__ out_acc,
                            float* __restrict__ den_acc) {
    int gwarp = (blockIdx.x * blockDim.x + threadIdx.x) >> 5;
    if (gwarp >= N_PROJ) return;
    int lane = threadIdx.x & 31;
    int src = esrc[gwarp];
    int tgt = etgt[gwarp];

    const float4* xlp = (const float4*)(xl + (size_t)src * 256);
    const float4* xrp = (const float4*)(xr + (size_t)tgt * 256);
    // lane covers float4 #lane (d = 4*lane..4*lane+3, head h1 = lane/8)
    // and float4 #(lane+32) (d = 128+4*lane.., head h2 = lane/8 + 4)
    float4 a0 = xlp[lane];
    float4 a1 = xlp[lane + 32];
    float4 r0 = xrp[lane];
    float4 r1 = xrp[lane + 32];

    int h1 = lane >> 3;
    int h2 = h1 + 4;
    const float4 w0 = *(const float4*)(att + h1 * 32 + ((lane & 7) << 2));
    const float4 w1 = *(const float4*)(att + h2 * 32 + ((lane & 7) << 2));

    // leaky_relu(x) = max(x,0) + 0.2*min(x,0)
    #define LREL(x) (fmaxf((x), 0.f) + 0.2f * fminf((x), 0.f))
    float p1 = LREL(a0.x + r0.x) * w0.x + LREL(a0.y + r0.y) * w0.y +
               LREL(a0.z + r0.z) * w0.z + LREL(a0.w + r0.w) * w0.w;
    float p2 = LREL(a1.x + r1.x) * w1.x + LREL(a1.y + r1.y) * w1.y +
               LREL(a1.z + r1.z) * w1.z + LREL(a1.w + r1.w) * w1.w;
    #undef LREL

    // reduce within 8-lane head groups (butterfly: every lane gets group sum)
    #pragma unroll
    for (int o = 4; o; o >>= 1) {
        p1 += __shfl_xor_sync(0xffffffffu, p1, o);
        p2 += __shfl_xor_sync(0xffffffffu, p2, o);
    }
    // softmax shift skipped: scores ~ N(0,0.3), exp() safe in fp32 (shift-invariant)
    float ex1 = expf(p1);
    float ex2 = expf(p2);

    if ((lane & 7) == 0) {
        atomicAdd(den_acc + (size_t)tgt * 8 + h1, ex1);
        atomicAdd(den_acc + (size_t)tgt * 8 + h2, ex2);
    }

    float* op = out_acc + (size_t)tgt * 256;
    int d0 = lane << 2;
    atomicAdd(op + d0 + 0, ex1 * a0.x);
    atomicAdd(op + d0 + 1, ex1 * a0.y);
    atomicAdd(op + d0 + 2, ex1 * a0.z);
    atomicAdd(op + d0 + 3, ex1 * a0.w);
    atomicAdd(op + 128 + d0 + 0, ex2 * a1.x);
    atomicAdd(op + 128 + d0 + 1, ex2 * a1.y);
    atomicAdd(op + 128 + d0 + 2, ex2 * a1.z);
    atomicAdd(op + 128 + d0 + 3, ex2 * a1.w);
}

// -------- finalize: x = prev + out/den + gat_bias; xskip=x; h=relu(LN2(x)) --------
__global__ void finalize_kernel(const float* __restrict__ prev,
                                const float* __restrict__ gat_bias,
                                const float* __restrict__ g2,
                                const float* __restrict__ b2,
                                const float* __restrict__ out_acc,
                                const float* __restrict__ den_acc,
                                float* __restrict__ xskip,
                                float* __restrict__ hbuf) {
    int row = blockIdx.x, t = threadIdx.x;
    size_t idx = (size_t)row * D_ + t;
    float den = den_acc[(size_t)row * 8 + (t >> 5)] + 1e-16f;
    float x = prev[idx] + out_acc[idx] / den + gat_bias[t];
    xskip[idx] = x;

    float s = x, q = x * x;
    #pragma unroll
    for (int o = 16; o; o >>= 1) {
        s += __shfl_xor_sync(0xffffffffu, s, o);
        q += __shfl_xor_sync(0xffffffffu, q, o);
    }
    __shared__ float ss[8], qq[8];
    if ((t & 31) == 0) { ss[t >> 5] = s; qq[t >> 5] = q; }
    __syncthreads();
    float tot = 0.f, totq = 0.f;
    #pragma unroll
    for (int w = 0; w < 8; w++) { tot += ss[w]; totq += qq[w]; }
    float mean = tot * (1.f / 256.f);
    float var  = totq * (1.f / 256.f) - mean * mean;
    float rstd = rsqrtf(var + 1e-5f);
    float y = (x - mean) * rstd * g2[t] + b2[t];
    hbuf[idx] = fmaxf(y, 0.f);
}

extern "C" void kernel_launch(void* const* d_in, const int* in_sizes, int n_in,
                              void* d_out, int out_size) {
    const float* proj     = (const float*)d_in[0];
    const float* prev     = (const float*)d_in[1];
    const float* Wl       = (const float*)d_in[2];
    const float* bl       = (const float*)d_in[3];
    const float* Wr       = (const float*)d_in[4];
    const float* br       = (const float*)d_in[5];
    const float* att      = (const float*)d_in[6];
    const float* gat_bias = (const float*)d_in[7];
    const float* ln1_g    = (const float*)d_in[8];
    const float* ln1_b    = (const float*)d_in[9];
    const float* ln2_g    = (const float*)d_in[10];
    const float* ln2_b    = (const float*)d_in[11];
    const float* mlp_W    = (const float*)d_in[12];
    const float* mlp_b    = (const float*)d_in[13];
    const int*   esrc     = (const int*)d_in[14];
    const int*   etgt     = (const int*)d_in[15];
    float* out = (float*)d_out;

    float *p_xl, *p_xagg, *p_xr, *p_out, *p_den, *p_xskip, *p_hbuf;
    cudaGetSymbolAddress((void**)&p_xl, g_xl);
    cudaGetSymbolAddress((void**)&p_xagg, g_xagg);
    cudaGetSymbolAddress((void**)&p_xr, g_xr);
    cudaGetSymbolAddress((void**)&p_out, g_out);
    cudaGetSymbolAddress((void**)&p_den, g_den);
    cudaGetSymbolAddress((void**)&p_xskip, g_xskip);
    cudaGetSymbolAddress((void**)&p_hbuf, g_hbuf);

    // 1) zero accumulators
    zero_kernel<<<(N_SP * D_ + 255) / 256, 256>>>(p_out, p_den);

    // 2) x_agg = relu(LN1(prev))
    ln_relu_kernel<<<N_SP, 256>>>(prev, ln1_g, ln1_b, p_xagg);

    // 3) xr = x_agg @ Wr + br
    {
        dim3 grid(256 / 64, N_SP / 64);
        gemm256_kernel<<<grid, 256>>>(p_xagg, Wr, br, nullptr, p_xr);
    }

    // 4) xl = proj @ Wl + bl
    {
        dim3 grid(256 / 64, N_PROJ / 64);
        gemm256_kernel<<<grid, 256>>>(proj, Wl, bl, nullptr, p_xl);
    }

    // 5) edge pass (one warp/edge)
    {
        int warps = N_PROJ;
        int blocks = (warps * 32 + 255) / 256;
        edge_kernel<<<blocks, 256>>>(esrc, etgt, att, p_xl, p_xr, p_out, p_den);
    }

    // 6) finalize: residual + LN2 + relu
    finalize_kernel<<<N_SP, 256>>>(prev, gat_bias, ln2_g, ln2_b,
                                   p_out, p_den, p_xskip, p_hbuf);

    // 7) out = xskip + hbuf @ mlp_W + mlp_b
    {
        dim3 grid(256 / 64, N_SP / 64);
        gemm256_kernel<<<grid, 256>>>(p_hbuf, mlp_W, mlp_b, p_xskip, out);
    }
}

// round 3
// speedup vs baseline: 2.6117x; 2.6117x over previous
#include <cuda_runtime.h>
#include <cstdint>

#define N_PROJ 400000
#define N_SP   40000
#define D_     256
#define H_     8
#define SP_PAD 40064   // 313 * 128

// -------- scratch (device globals; zero-initialized, no runtime alloc) --------
__device__ float g_xl[(size_t)N_PROJ * D_];     // proj @ Wl + bl
__device__ float g_xagg[(size_t)SP_PAD * D_];   // relu(LN1(prev))
__device__ float g_xr[(size_t)SP_PAD * D_];     // xagg @ Wr + br
__device__ float g_out[(size_t)N_SP * D_];      // sum_e ex * xl
__device__ float g_den[(size_t)N_SP * H_];      // sum_e ex
__device__ float g_xskip[(size_t)SP_PAD * D_];
__device__ float g_hbuf[(size_t)SP_PAD * D_];

// ======================= helpers =======================
static __device__ __forceinline__ uint32_t smem_u32(const void* p) {
    uint32_t a;
    asm("{ .reg .u64 t; cvta.to.shared.u64 t, %1; cvt.u32.u64 %0, t; }"
        : "=r"(a) : "l"(p));
    return a;
}
static __device__ __forceinline__ uint32_t f2tf32(float f) {
    uint32_t r;
    asm("cvt.rna.tf32.f32 %0, %1;" : "=r"(r) : "f"(f));
    return r;
}
#define CPA16(dst, src) \
    asm volatile("cp.async.cg.shared.global [%0], [%1], 16;" :: "r"(dst), "l"(src))
#define CPA_COMMIT() asm volatile("cp.async.commit_group;" ::: "memory")
#define CPA_WAIT(n)  asm volatile("cp.async.wait_group %0;" :: "n"(n) : "memory")

static __device__ __forceinline__ void mma_tf32(float* c, const uint32_t* a,
                                                const uint32_t* b) {
    asm volatile(
        "mma.sync.aligned.m16n8k8.row.col.f32.tf32.tf32.f32 "
        "{%0,%1,%2,%3}, {%4,%5,%6,%7}, {%8,%9}, {%0,%1,%2,%3};"
        : "+f"(c[0]), "+f"(c[1]), "+f"(c[2]), "+f"(c[3])
        : "r"(a[0]), "r"(a[1]), "r"(a[2]), "r"(a[3]), "r"(b[0]), "r"(b[1]));
}

// ======================= tf32 mma.sync GEMM =======================
// C[M,256] = A[M,256] @ W[256,256] + bias (+skip)
// CTA: 128x128 tile, 4 warps (2x2), warp tile 64x64, BK=32, cp.async 2-stage.
#define BM 128
#define BN 128
#define BK 32
#define GK 256
#define AS_STRIDE 36    // floats; banks (4g+t) conflict-free
#define BS_STRIDE 136   // floats; banks (8t+g) conflict-free
#define A_WORDS (BM * AS_STRIDE)   // 4608
#define B_WORDS (BK * BS_STRIDE)   // 4352
#define STAGE_WORDS (A_WORDS + B_WORDS)
#define GEMM_SMEM (2 * STAGE_WORDS * 4)   // 71680 B

__global__ void __launch_bounds__(128)
mma_gemm(const float* __restrict__ A, const float* __restrict__ W,
         const float* __restrict__ bias, const float* __restrict__ skip,
         float* __restrict__ C, int Mtot)
{
    extern __shared__ float sm[];
    const int tid = threadIdx.x;
    const int wid = tid >> 5, lane = tid & 31;
    const int g = lane >> 2, t = lane & 3;
    const int wm = (wid >> 1) * 64;     // warp m offset in tile
    const int wn = (wid & 1) * 64;      // warp n offset in tile
    const int row0 = blockIdx.y * BM;
    const int col0 = blockIdx.x * BN;

    float c[4][8][4];
    #pragma unroll
    for (int i = 0; i < 4; i++)
        #pragma unroll
        for (int j = 0; j < 8; j++)
            { c[i][j][0] = 0.f; c[i][j][1] = 0.f; c[i][j][2] = 0.f; c[i][j][3] = 0.f; }

    uint32_t sbase = smem_u32(sm);

    // --- async load of one stage ---
    // A tile: 128 rows x 32 floats (8 float4/row); B tile: 32 rows x 128 floats
    auto issue_stage = [&](int kt, int buf) {
        uint32_t abase = sbase + buf * STAGE_WORDS * 4;
        uint32_t bbase = abase + A_WORDS * 4;
        int k0 = kt * BK;
        #pragma unroll
        for (int i = 0; i < 8; i++) {
            int idx = i * 128 + tid;
            int r = idx >> 3, cq = idx & 7;
            const float* src = A + (size_t)(row0 + r) * GK + k0 + cq * 4;
            CPA16(abase + (r * AS_STRIDE + cq * 4) * 4, src);
        }
        #pragma unroll
        for (int i = 0; i < 8; i++) {
            int idx = i * 128 + tid;
            int r = idx >> 5, cq = idx & 31;
            const float* src = W + (size_t)(k0 + r) * GK + col0 + cq * 4;
            CPA16(bbase + (r * BS_STRIDE + cq * 4) * 4, src);
        }
        CPA_COMMIT();
    };

    issue_stage(0, 0);

    for (int kt = 0; kt < GK / BK; ++kt) {
        int buf = kt & 1;
        if (kt + 1 < GK / BK) issue_stage(kt + 1, buf ^ 1);
        if (kt + 1 < GK / BK) { CPA_WAIT(1); } else { CPA_WAIT(0); }
        __syncthreads();

        const float* As = sm + buf * STAGE_WORDS;
        const float* Bs = As + A_WORDS;

        #pragma unroll
        for (int k8 = 0; k8 < BK / 8; k8++) {
            int kk = k8 * 8;
            uint32_t af[4][4], bf[8][2];
            #pragma unroll
            for (int mt = 0; mt < 4; mt++) {
                int m = wm + mt * 16;
                af[mt][0] = f2tf32(As[(m + g) * AS_STRIDE + kk + t]);
                af[mt][1] = f2tf32(As[(m + g + 8) * AS_STRIDE + kk + t]);
                af[mt][2] = f2tf32(As[(m + g) * AS_STRIDE + kk + t + 4]);
                af[mt][3] = f2tf32(As[(m + g + 8) * AS_STRIDE + kk + t + 4]);
            }
            #pragma unroll
            for (int nt = 0; nt < 8; nt++) {
                int n = wn + nt * 8;
                bf[nt][0] = f2tf32(Bs[(kk + t) * BS_STRIDE + n + g]);
                bf[nt][1] = f2tf32(Bs[(kk + t + 4) * BS_STRIDE + n + g]);
            }
            #pragma unroll
            for (int mt = 0; mt < 4; mt++)
                #pragma unroll
                for (int nt = 0; nt < 8; nt++)
                    mma_tf32(c[mt][nt], af[mt], bf[nt]);
        }
        __syncthreads();
    }

    // --- epilogue ---
    #pragma unroll
    for (int mt = 0; mt < 4; mt++) {
        int r0 = row0 + wm + mt * 16 + g;
        int r1 = r0 + 8;
        #pragma unroll
        for (int nt = 0; nt < 8; nt++) {
            int cc = col0 + wn + nt * 8 + 2 * t;
            float b0 = bias[cc], b1 = bias[cc + 1];
            if (r0 < Mtot) {
                float2 v;
                v.x = c[mt][nt][0] + b0;
                v.y = c[mt][nt][1] + b1;
                if (skip) {
                    const float2 s2 = *(const float2*)(skip + (size_t)r0 * D_ + cc);
                    v.x += s2.x; v.y += s2.y;
                }
                *(float2*)(C + (size_t)r0 * D_ + cc) = v;
            }
            if (r1 < Mtot) {
                float2 v;
                v.x = c[mt][nt][2] + b0;
                v.y = c[mt][nt][3] + b1;
                if (skip) {
                    const float2 s2 = *(const float2*)(skip + (size_t)r1 * D_ + cc);
                    v.x += s2.x; v.y += s2.y;
                }
                *(float2*)(C + (size_t)r1 * D_ + cc) = v;
            }
        }
    }
}

// ======================= zero accumulators =======================
__global__ void zero_kernel(float* out_acc, float* den_acc) {
    int i = blockIdx.x * blockDim.x + threadIdx.x;
    if (i < N_SP * D_) out_acc[i] = 0.f;
    if (i < N_SP * H_) den_acc[i] = 0.f;
}

// ======================= LayerNorm + ReLU =======================
__global__ void ln_relu_kernel(const float* __restrict__ x,
                               const float* __restrict__ g,
                               const float* __restrict__ b,
                               float* __restrict__ out) {
    int row = blockIdx.x, t = threadIdx.x;
    size_t idx = (size_t)row * D_ + t;
    float v = x[idx];
    float s = v, q = v * v;
    #pragma unroll
    for (int o = 16; o; o >>= 1) {
        s += __shfl_xor_sync(0xffffffffu, s, o);
        q += __shfl_xor_sync(0xffffffffu, q, o);
    }
    __shared__ float ss[8], qq[8];
    if ((t & 31) == 0) { ss[t >> 5] = s; qq[t >> 5] = q; }
    __syncthreads();
    float tot = 0.f, totq = 0.f;
    #pragma unroll
    for (int w = 0; w < 8; w++) { tot += ss[w]; totq += qq[w]; }
    float mean = tot * (1.f / 256.f);
    float var  = totq * (1.f / 256.f) - mean * mean;
    float rstd = rsqrtf(var + 1e-5f);
    float y = (v - mean) * rstd * g[t] + b[t];
    out[idx] = fmaxf(y, 0.f);
}

// ======================= edge pass (one warp/edge) =======================
__global__ void edge_kernel(const int* __restrict__ esrc,
                            const int* __restrict__ etgt,
                            const float* __restrict__ att,
                            const float* __restrict__ xl,
                            const float* __restrict__ xr,
                            float* __restrict__ out_acc,
                            float* __restrict__ den_acc) {
    int gwarp = (blockIdx.x * blockDim.x + threadIdx.x) >> 5;
    if (gwarp >= N_PROJ) return;
    int lane = threadIdx.x & 31;
    int src = esrc[gwarp];
    int tgt = etgt[gwarp];

    const float4* xlp = (const float4*)(xl + (size_t)src * 256);
    const float4* xrp = (const float4*)(xr + (size_t)tgt * 256);
    float4 a0 = xlp[lane];
    float4 a1 = xlp[lane + 32];
    float4 r0 = xrp[lane];
    float4 r1 = xrp[lane + 32];

    int h1 = lane >> 3;
    int h2 = h1 + 4;
    const float4 w0 = *(const float4*)(att + h1 * 32 + ((lane & 7) << 2));
    const float4 w1 = *(const float4*)(att + h2 * 32 + ((lane & 7) << 2));

    #define LREL(x) (fmaxf((x), 0.f) + 0.2f * fminf((x), 0.f))
    float p1 = LREL(a0.x + r0.x) * w0.x + LREL(a0.y + r0.y) * w0.y +
               LREL(a0.z + r0.z) * w0.z + LREL(a0.w + r0.w) * w0.w;
    float p2 = LREL(a1.x + r1.x) * w1.x + LREL(a1.y + r1.y) * w1.y +
               LREL(a1.z + r1.z) * w1.z + LREL(a1.w + r1.w) * w1.w;
    #undef LREL

    #pragma unroll
    for (int o = 4; o; o >>= 1) {
        p1 += __shfl_xor_sync(0xffffffffu, p1, o);
        p2 += __shfl_xor_sync(0xffffffffu, p2, o);
    }
    float ex1 = expf(p1);
    float ex2 = expf(p2);

    if ((lane & 7) == 0) {
        atomicAdd(den_acc + (size_t)tgt * 8 + h1, ex1);
        atomicAdd(den_acc + (size_t)tgt * 8 + h2, ex2);
    }

    float* op = out_acc + (size_t)tgt * 256;
    int d0 = lane << 2;
    atomicAdd(op + d0 + 0, ex1 * a0.x);
    atomicAdd(op + d0 + 1, ex1 * a0.y);
    atomicAdd(op + d0 + 2, ex1 * a0.z);
    atomicAdd(op + d0 + 3, ex1 * a0.w);
    atomicAdd(op + 128 + d0 + 0, ex2 * a1.x);
    atomicAdd(op + 128 + d0 + 1, ex2 * a1.y);
    atomicAdd(op + 128 + d0 + 2, ex2 * a1.z);
    atomicAdd(op + 128 + d0 + 3, ex2 * a1.w);
}

// ======================= finalize =======================
__global__ void finalize_kernel(const float* __restrict__ prev,
                                const float* __restrict__ gat_bias,
                                const float* __restrict__ g2,
                                const float* __restrict__ b2,
                                const float* __restrict__ out_acc,
                                const float* __restrict__ den_acc,
                                float* __restrict__ xskip,
                                float* __restrict__ hbuf) {
    int row = blockIdx.x, t = threadIdx.x;
    size_t idx = (size_t)row * D_ + t;
    float den = den_acc[(size_t)row * 8 + (t >> 5)] + 1e-16f;
    float x = prev[idx] + out_acc[idx] / den + gat_bias[t];
    xskip[idx] = x;

    float s = x, q = x * x;
    #pragma unroll
    for (int o = 16; o; o >>= 1) {
        s += __shfl_xor_sync(0xffffffffu, s, o);
        q += __shfl_xor_sync(0xffffffffu, q, o);
    }
    __shared__ float ss[8], qq[8];
    if ((t & 31) == 0) { ss[t >> 5] = s; qq[t >> 5] = q; }
    __syncthreads();
    float tot = 0.f, totq = 0.f;
    #pragma unroll
    for (int w = 0; w < 8; w++) { tot += ss[w]; totq += qq[w]; }
    float mean = tot * (1.f / 256.f);
    float var  = totq * (1.f / 256.f) - mean * mean;
    float rstd = rsqrtf(var + 1e-5f);
    float y = (x - mean) * rstd * g2[t] + b2[t];
    hbuf[idx] = fmaxf(y, 0.f);
}

// ======================= launch =======================
extern "C" void kernel_launch(void* const* d_in, const int* in_sizes, int n_in,
                              void* d_out, int out_size) {
    const float* proj     = (const float*)d_in[0];
    const float* prev     = (const float*)d_in[1];
    const float* Wl       = (const float*)d_in[2];
    const float* bl       = (const float*)d_in[3];
    const float* Wr       = (const float*)d_in[4];
    const float* br       = (const float*)d_in[5];
    const float* att      = (const float*)d_in[6];
    const float* gat_bias = (const float*)d_in[7];
    const float* ln1_g    = (const float*)d_in[8];
    const float* ln1_b    = (const float*)d_in[9];
    const float* ln2_g    = (const float*)d_in[10];
    const float* ln2_b    = (const float*)d_in[11];
    const float* mlp_W    = (const float*)d_in[12];
    const float* mlp_b    = (const float*)d_in[13];
    const int*   esrc     = (const int*)d_in[14];
    const int*   etgt     = (const int*)d_in[15];
    float* out = (float*)d_out;

    float *p_xl, *p_xagg, *p_xr, *p_out, *p_den, *p_xskip, *p_hbuf;
    cudaGetSymbolAddress((void**)&p_xl, g_xl);
    cudaGetSymbolAddress((void**)&p_xagg, g_xagg);
    cudaGetSymbolAddress((void**)&p_xr, g_xr);
    cudaGetSymbolAddress((void**)&p_out, g_out);
    cudaGetSymbolAddress((void**)&p_den, g_den);
    cudaGetSymbolAddress((void**)&p_xskip, g_xskip);
    cudaGetSymbolAddress((void**)&p_hbuf, g_hbuf);

    cudaFuncSetAttribute(mma_gemm, cudaFuncAttributeMaxDynamicSharedMemorySize, GEMM_SMEM);

    // 1) zero accumulators
    zero_kernel<<<(N_SP * D_ + 255) / 256, 256>>>(p_out, p_den);

    // 2) x_agg = relu(LN1(prev))
    ln_relu_kernel<<<N_SP, 256>>>(prev, ln1_g, ln1_b, p_xagg);

    // 3) xr = x_agg @ Wr + br  (313 M-tiles, tail rows are zero-padded scratch)
    {
        dim3 grid(D_ / BN, SP_PAD / BM);
        mma_gemm<<<grid, 128, GEMM_SMEM>>>(p_xagg, Wr, br, nullptr, p_xr, N_SP);
    }

    // 4) xl = proj @ Wl + bl   (3125 M-tiles exact)
    {
        dim3 grid(D_ / BN, N_PROJ / BM);
        mma_gemm<<<grid, 128, GEMM_SMEM>>>(proj, Wl, bl, nullptr, p_xl, N_PROJ);
    }

    // 5) edge pass
    edge_kernel<<<(N_PROJ * 32 + 255) / 256, 256>>>(esrc, etgt, att, p_xl, p_xr, p_out, p_den);

    // 6) finalize: residual + LN2 + relu
    finalize_kernel<<<N_SP, 256>>>(prev, gat_bias, ln2_g, ln2_b,
                                   p_out, p_den, p_xskip, p_hbuf);

    // 7) out = xskip + hbuf @ mlp_W + mlp_b
    {
        dim3 grid(D_ / BN, SP_PAD / BM);
        mma_gemm<<<grid, 128, GEMM_SMEM>>>(p_hbuf, mlp_W, mlp_b, p_xskip, out, N_SP);
    }
}

// round 4
// speedup vs baseline: 3.0755x; 1.1776x over previous
#include <cuda_runtime.h>
#include <cstdint>

#define N_PROJ 400000
#define N_SP   40000
#define D_     256
#define H_     8
#define SP_PAD 40064   // 313 * 128

// -------- scratch (device globals; no runtime alloc) --------
__device__ float g_xl[(size_t)N_PROJ * D_];
__device__ float g_xagg[(size_t)SP_PAD * D_];
__device__ float g_xr[(size_t)SP_PAD * D_];
__device__ float g_out[(size_t)N_SP * D_];
__device__ float g_den[(size_t)N_SP * H_];
__device__ float g_xskip[(size_t)SP_PAD * D_];
__device__ float g_hbuf[(size_t)SP_PAD * D_];

// ======================= helpers =======================
static __device__ __forceinline__ uint32_t smem_u32(const void* p) {
    uint32_t a;
    asm("{ .reg .u64 t; cvta.to.shared.u64 t, %1; cvt.u32.u64 %0, t; }"
        : "=r"(a) : "l"(p));
    return a;
}
static __device__ __forceinline__ uint32_t f2tf32(float f) {
    uint32_t r;
    asm("cvt.rna.tf32.f32 %0, %1;" : "=r"(r) : "f"(f));
    return r;
}
#define CPA16(dst, src) \
    asm volatile("cp.async.cg.shared.global [%0], [%1], 16;" :: "r"(dst), "l"(src))
#define CPA_COMMIT() asm volatile("cp.async.commit_group;" ::: "memory")
#define CPA_WAIT(n)  asm volatile("cp.async.wait_group %0;" :: "n"(n) : "memory")

static __device__ __forceinline__ void mma_tf32(float* c, const uint32_t* a,
                                                const uint32_t* b) {
    asm volatile(
        "mma.sync.aligned.m16n8k8.row.col.f32.tf32.tf32.f32 "
        "{%0,%1,%2,%3}, {%4,%5,%6,%7}, {%8,%9}, {%0,%1,%2,%3};"
        : "+f"(c[0]), "+f"(c[1]), "+f"(c[2]), "+f"(c[3])
        : "r"(a[0]), "r"(a[1]), "r"(a[2]), "r"(a[3]), "r"(b[0]), "r"(b[1]));
}
#define REDV4(p, x, y, z, w) \
    asm volatile("red.global.add.v4.f32 [%0], {%1,%2,%3,%4};" \
                 :: "l"(p), "f"(x), "f"(y), "f"(z), "f"(w) : "memory")

// ======================= tf32 mma.sync GEMM =======================
// C[M,256] = A[M,256] @ W[256,256] + bias (+skip)
// CTA: 128x128 tile, 256 threads / 8 warps (2x4), warp tile 64x32, BK=32, 2-stage.
#define BM 128
#define BN 128
#define BK 32
#define GK 256
#define AS_STRIDE 36
#define BS_STRIDE 136
#define A_WORDS (BM * AS_STRIDE)   // 4608
#define B_WORDS (BK * BS_STRIDE)   // 4352
#define STAGE_WORDS (A_WORDS + B_WORDS)
#define GEMM_SMEM (2 * STAGE_WORDS * 4)   // 71680 B

__global__ void __launch_bounds__(256)
mma_gemm(const float* __restrict__ A, const float* __restrict__ W,
         const float* __restrict__ bias, const float* __restrict__ skip,
         float* __restrict__ C, int Mtot)
{
    extern __shared__ float sm[];
    const int tid = threadIdx.x;
    const int wid = tid >> 5, lane = tid & 31;
    const int g = lane >> 2, t = lane & 3;
    const int wm = (wid >> 2) * 64;     // 2 warps in m
    const int wn = (wid & 3) * 32;      // 4 warps in n
    const int row0 = blockIdx.y * BM;
    const int col0 = blockIdx.x * BN;

    float c[4][4][4];
    #pragma unroll
    for (int i = 0; i < 4; i++)
        #pragma unroll
        for (int j = 0; j < 4; j++)
            { c[i][j][0] = 0.f; c[i][j][1] = 0.f; c[i][j][2] = 0.f; c[i][j][3] = 0.f; }

    uint32_t sbase = smem_u32(sm);

    // A tile: 128 rows x 32 floats; B tile: 32 rows x 128 floats (4 float4/thread each)
    auto issue_stage = [&](int kt, int buf) {
        uint32_t abase = sbase + buf * STAGE_WORDS * 4;
        uint32_t bbase = abase + A_WORDS * 4;
        int k0 = kt * BK;
        #pragma unroll
        for (int i = 0; i < 4; i++) {
            int idx = i * 256 + tid;
            int r = idx >> 3, cq = idx & 7;
            CPA16(abase + (r * AS_STRIDE + cq * 4) * 4,
                  A + (size_t)(row0 + r) * GK + k0 + cq * 4);
        }
        #pragma unroll
        for (int i = 0; i < 4; i++) {
            int idx = i * 256 + tid;
            int r = idx >> 5, cq = idx & 31;
            CPA16(bbase + (r * BS_STRIDE + cq * 4) * 4,
                  W + (size_t)(k0 + r) * GK + col0 + cq * 4);
        }
        CPA_COMMIT();
    };

    issue_stage(0, 0);

    for (int kt = 0; kt < GK / BK; ++kt) {
        int buf = kt & 1;
        if (kt + 1 < GK / BK) { issue_stage(kt + 1, buf ^ 1); CPA_WAIT(1); }
        else                  { CPA_WAIT(0); }
        __syncthreads();

        const float* As = sm + buf * STAGE_WORDS;
        const float* Bs = As + A_WORDS;

        #pragma unroll
        for (int k8 = 0; k8 < BK / 8; k8++) {
            int kk = k8 * 8;
            uint32_t af[4][4], bf[4][2];
            #pragma unroll
            for (int mt = 0; mt < 4; mt++) {
                int m = wm + mt * 16;
                af[mt][0] = f2tf32(As[(m + g) * AS_STRIDE + kk + t]);
                af[mt][1] = f2tf32(As[(m + g + 8) * AS_STRIDE + kk + t]);
                af[mt][2] = f2tf32(As[(m + g) * AS_STRIDE + kk + t + 4]);
                af[mt][3] = f2tf32(As[(m + g + 8) * AS_STRIDE + kk + t + 4]);
            }
            #pragma unroll
            for (int nt = 0; nt < 4; nt++) {
                int n = wn + nt * 8;
                bf[nt][0] = f2tf32(Bs[(kk + t) * BS_STRIDE + n + g]);
                bf[nt][1] = f2tf32(Bs[(kk + t + 4) * BS_STRIDE + n + g]);
            }
            #pragma unroll
            for (int mt = 0; mt < 4; mt++)
                #pragma unroll
                for (int nt = 0; nt < 4; nt++)
                    mma_tf32(c[mt][nt], af[mt], bf[nt]);
        }
        __syncthreads();
    }

    // --- epilogue ---
    #pragma unroll
    for (int mt = 0; mt < 4; mt++) {
        int r0 = row0 + wm + mt * 16 + g;
        int r1 = r0 + 8;
        #pragma unroll
        for (int nt = 0; nt < 4; nt++) {
            int cc = col0 + wn + nt * 8 + 2 * t;
            float b0 = bias[cc], b1 = bias[cc + 1];
            if (r0 < Mtot) {
                float2 v = { c[mt][nt][0] + b0, c[mt][nt][1] + b1 };
                if (skip) {
                    const float2 s2 = *(const float2*)(skip + (size_t)r0 * D_ + cc);
                    v.x += s2.x; v.y += s2.y;
                }
                *(float2*)(C + (size_t)r0 * D_ + cc) = v;
            }
            if (r1 < Mtot) {
                float2 v = { c[mt][nt][2] + b0, c[mt][nt][3] + b1 };
                if (skip) {
                    const float2 s2 = *(const float2*)(skip + (size_t)r1 * D_ + cc);
                    v.x += s2.x; v.y += s2.y;
                }
                *(float2*)(C + (size_t)r1 * D_ + cc) = v;
            }
        }
    }
}

// ======================= zero accumulators =======================
__global__ void zero_kernel(float* out_acc, float* den_acc) {
    int i = blockIdx.x * blockDim.x + threadIdx.x;
    if (i < N_SP * D_) out_acc[i] = 0.f;
    if (i < N_SP * H_) den_acc[i] = 0.f;
}

// ======================= LayerNorm + ReLU =======================
__global__ void ln_relu_kernel(const float* __restrict__ x,
                               const float* __restrict__ g,
                               const float* __restrict__ b,
                               float* __restrict__ out) {
    int row = blockIdx.x, t = threadIdx.x;
    size_t idx = (size_t)row * D_ + t;
    float v = x[idx];
    float s = v, q = v * v;
    #pragma unroll
    for (int o = 16; o; o >>= 1) {
        s += __shfl_xor_sync(0xffffffffu, s, o);
        q += __shfl_xor_sync(0xffffffffu, q, o);
    }
    __shared__ float ss[8], qq[8];
    if ((t & 31) == 0) { ss[t >> 5] = s; qq[t >> 5] = q; }
    __syncthreads();
    float tot = 0.f, totq = 0.f;
    #pragma unroll
    for (int w = 0; w < 8; w++) { tot += ss[w]; totq += qq[w]; }
    float mean = tot * (1.f / 256.f);
    float var  = totq * (1.f / 256.f) - mean * mean;
    float rstd = rsqrtf(var + 1e-5f);
    float y = (v - mean) * rstd * g[t] + b[t];
    out[idx] = fmaxf(y, 0.f);
}

// ======================= edge pass (one warp/edge) =======================
__global__ void edge_kernel(const int* __restrict__ esrc,
                            const int* __restrict__ etgt,
                            const float* __restrict__ att,
                            const float* __restrict__ xl,
                            const float* __restrict__ xr,
                            float* __restrict__ out_acc,
                            float* __restrict__ den_acc) {
    int gwarp = (blockIdx.x * blockDim.x + threadIdx.x) >> 5;
    if (gwarp >= N_PROJ) return;
    int lane = threadIdx.x & 31;
    int src = esrc[gwarp];
    int tgt = etgt[gwarp];

    const float4* xlp = (const float4*)(xl + (size_t)src * 256);
    const float4* xrp = (const float4*)(xr + (size_t)tgt * 256);
    float4 a0 = xlp[lane];
    float4 a1 = xlp[lane + 32];
    float4 r0 = xrp[lane];
    float4 r1 = xrp[lane + 32];

    int h1 = lane >> 3;
    int h2 = h1 + 4;
    const float4 w0 = *(const float4*)(att + h1 * 32 + ((lane & 7) << 2));
    const float4 w1 = *(const float4*)(att + h2 * 32 + ((lane & 7) << 2));

    #define LREL(x) (fmaxf((x), 0.f) + 0.2f * fminf((x), 0.f))
    float p1 = LREL(a0.x + r0.x) * w0.x + LREL(a0.y + r0.y) * w0.y +
               LREL(a0.z + r0.z) * w0.z + LREL(a0.w + r0.w) * w0.w;
    float p2 = LREL(a1.x + r1.x) * w1.x + LREL(a1.y + r1.y) * w1.y +
               LREL(a1.z + r1.z) * w1.z + LREL(a1.w + r1.w) * w1.w;
    #undef LREL

    #pragma unroll
    for (int o = 4; o; o >>= 1) {
        p1 += __shfl_xor_sync(0xffffffffu, p1, o);
        p2 += __shfl_xor_sync(0xffffffffu, p2, o);
    }
    float ex1 = expf(p1);
    float ex2 = expf(p2);

    if ((lane & 7) == 0) {
        atomicAdd(den_acc + (size_t)tgt * 8 + h1, ex1);
        atomicAdd(den_acc + (size_t)tgt * 8 + h2, ex2);
    }

    float* op = out_acc + (size_t)tgt * 256;
    int d0 = lane << 2;
    REDV4(op + d0,       ex1 * a0.x, ex1 * a0.y, ex1 * a0.z, ex1 * a0.w);
    REDV4(op + 128 + d0, ex2 * a1.x, ex2 * a1.y, ex2 * a1.z, ex2 * a1.w);
}

// ======================= finalize =======================
__global__ void finalize_kernel(const float* __restrict__ prev,
                                const float* __restrict__ gat_bias,
                                const float* __restrict__ g2,
                                const float* __restrict__ b2,
                                const float* __restrict__ out_acc,
                                const float* __restrict__ den_acc,
                                float* __restrict__ xskip,
                                float* __restrict__ hbuf) {
    int row = blockIdx.x, t = threadIdx.x;
    size_t idx = (size_t)row * D_ + t;
    float den = den_acc[(size_t)row * 8 + (t >> 5)] + 1e-16f;
    float x = prev[idx] + out_acc[idx] / den + gat_bias[t];
    xskip[idx] = x;

    float s = x, q = x * x;
    #pragma unroll
    for (int o = 16; o; o >>= 1) {
        s += __shfl_xor_sync(0xffffffffu, s, o);
        q += __shfl_xor_sync(0xffffffffu, q, o);
    }
    __shared__ float ss[8], qq[8];
    if ((t & 31) == 0) { ss[t >> 5] = s; qq[t >> 5] = q; }
    __syncthreads();
    float tot = 0.f, totq = 0.f;
    #pragma unroll
    for (int w = 0; w < 8; w++) { tot += ss[w]; totq += qq[w]; }
    float mean = tot * (1.f / 256.f);
    float var  = totq * (1.f / 256.f) - mean * mean;
    float rstd = rsqrtf(var + 1e-5f);
    float y = (x - mean) * rstd * g2[t] + b2[t];
    hbuf[idx] = fmaxf(y, 0.f);
}

// ======================= launch =======================
extern "C" void kernel_launch(void* const* d_in, const int* in_sizes, int n_in,
                              void* d_out, int out_size) {
    const float* proj     = (const float*)d_in[0];
    const float* prev     = (const float*)d_in[1];
    const float* Wl       = (const float*)d_in[2];
    const float* bl       = (const float*)d_in[3];
    const float* Wr       = (const float*)d_in[4];
    const float* br       = (const float*)d_in[5];
    const float* att      = (const float*)d_in[6];
    const float* gat_bias = (const float*)d_in[7];
    const float* ln1_g    = (const float*)d_in[8];
    const float* ln1_b    = (const float*)d_in[9];
    const float* ln2_g    = (const float*)d_in[10];
    const float* ln2_b    = (const float*)d_in[11];
    const float* mlp_W    = (const float*)d_in[12];
    const float* mlp_b    = (const float*)d_in[13];
    const int*   esrc     = (const int*)d_in[14];
    const int*   etgt     = (const int*)d_in[15];
    float* out = (float*)d_out;

    float *p_xl, *p_xagg, *p_xr, *p_out, *p_den, *p_xskip, *p_hbuf;
    cudaGetSymbolAddress((void**)&p_xl, g_xl);
    cudaGetSymbolAddress((void**)&p_xagg, g_xagg);
    cudaGetSymbolAddress((void**)&p_xr, g_xr);
    cudaGetSymbolAddress((void**)&p_out, g_out);
    cudaGetSymbolAddress((void**)&p_den, g_den);
    cudaGetSymbolAddress((void**)&p_xskip, g_xskip);
    cudaGetSymbolAddress((void**)&p_hbuf, g_hbuf);

    cudaFuncSetAttribute(mma_gemm, cudaFuncAttributeMaxDynamicSharedMemorySize, GEMM_SMEM);

    zero_kernel<<<(N_SP * D_ + 255) / 256, 256>>>(p_out, p_den);

    ln_relu_kernel<<<N_SP, 256>>>(prev, ln1_g, ln1_b, p_xagg);

    {   // xr = x_agg @ Wr + br
        dim3 grid(D_ / BN, SP_PAD / BM);
        mma_gemm<<<grid, 256, GEMM_SMEM>>>(p_xagg, Wr, br, nullptr, p_xr, N_SP);
    }
    {   // xl = proj @ Wl + bl
        dim3 grid(D_ / BN, N_PROJ / BM);
        mma_gemm<<<grid, 256, GEMM_SMEM>>>(proj, Wl, bl, nullptr, p_xl, N_PROJ);
    }

    edge_kernel<<<(N_PROJ * 32 + 255) / 256, 256>>>(esrc, etgt, att, p_xl, p_xr, p_out, p_den);

    finalize_kernel<<<N_SP, 256>>>(prev, gat_bias, ln2_g, ln2_b,
                                   p_out, p_den, p_xskip, p_hbuf);

    {   // out = xskip + hbuf @ mlp_W + mlp_b
        dim3 grid(D_ / BN, SP_PAD / BM);
        mma_gemm<<<grid, 256, GEMM_SMEM>>>(p_hbuf, mlp_W, mlp_b, p_xskip, out, N_SP);
    }
}